// round 9
// baseline (speedup 1.0000x reference)
#include <cuda_runtime.h>
#include <cuda_bf16.h>

#define MAX_ROWS 8192
#define NTHR 320          // 8000 float4 per row / 320 = exactly 25 per thread
#define NWARP (NTHR / 32)
#define PD 8              // prefetch distance in chunks (8*512B*~54 warps ≈ 220KB/SM in flight)

__device__ double g_row_loss[MAX_ROWS];
__device__ unsigned int g_done = 0;   // self-resets -> graph-replay safe

__device__ __forceinline__ float ex2(float x) {
    float y;
    asm("ex2.approx.f32 %0, %1;" : "=f"(y) : "f"(x));
    return y;
}
__device__ __forceinline__ void pf_l2(const void* p) {
    asm volatile("prefetch.global.L2 [%0];" :: "l"(p));
}

// One 320-thread block per row. R8 post-mortem: all designs were capped by
// SUSTAINED in-flight DRAM bytes (~27KB/SM at pipeline depth 1 -> queueing
// equilibrium at ~4.7TB/s). prefetch.global.L2 is scoreboard-free and
// register-free: it raises in-flight depth to PD chunks per warp while the
// demand LDG only has to cover L2-hit latency.
__global__ void __launch_bounds__(NTHR, 6) cosarc_fused_kernel(
    const float* __restrict__ preds,
    const int* __restrict__ labels,     // int32 (JAX x64 disabled)
    float* __restrict__ out,
    int V, int B)
{
    const int tid = threadIdx.x;
    const int wid = tid >> 5;
    const int lid = tid & 31;
    const int row = blockIdx.x;
    const float* rp = preds + (size_t)row * (size_t)V;

    const float C = 30.0f * 1.4426950408889634f;   // exp(30x) = exp2(C*x)
    float s0 = 0.f, s1 = 0.f, s2 = 0.f, s3 = 0.f;

    if (V == 32000) {
        const float4* p4 = reinterpret_cast<const float4*>(rp) + tid;

        // Prime the L2 pipeline: first PD chunks.
        #pragma unroll
        for (int k = 0; k < PD; k++)
            pf_l2(p4 + k * NTHR);

        #pragma unroll
        for (int k = 0; k < 25; k++) {
            if (k + PD < 25) pf_l2(p4 + (k + PD) * NTHR);   // stay PD ahead
            float4 v = __ldg(p4 + k * NTHR);                 // L2 hit by now
            s0 += ex2(v.x * C);
            s1 += ex2(v.y * C);
            s2 += ex2(v.z * C);
            s3 += ex2(v.w * C);
        }
    } else {
        const float4* p4 = reinterpret_cast<const float4*>(rp);
        const int n4 = V >> 2;
        for (int i = tid; i < n4; i += NTHR) {
            if (i + PD * NTHR < n4) pf_l2(&p4[i + PD * NTHR]);
            float4 v = __ldg(&p4[i]);
            s0 += ex2(v.x * C);
            s1 += ex2(v.y * C);
            s2 += ex2(v.z * C);
            s3 += ex2(v.w * C);
        }
        for (int j = (n4 << 2) + tid; j < V; j += NTHR)
            s0 += ex2(rp[j] * C);
    }

    float sum = (s0 + s1) + (s2 + s3);

    #pragma unroll
    for (int o = 16; o > 0; o >>= 1)
        sum += __shfl_xor_sync(0xffffffffu, sum, o);

    __shared__ float warpsum[NWARP];
    if (lid == 0) warpsum[wid] = sum;
    __syncthreads();

    if (tid == 0) {
        float tot = 0.f;
        #pragma unroll
        for (int w = 0; w < NWARP; w++) tot += warpsum[w];

        int lab = labels[row];
        if (lab < 0) lab = 0;
        if (lab >= V) lab = V - 1;
        const float target = rp[lab];

        double sum_others = (double)tot - (double)ex2(target * C);

        const double EPS = 1e-12;
        const double PI  = 3.14159265358979323846;
        double t = (double)target;
        t = fmin(fmax(t, -1.0 + EPS), 1.0 - EPS);
        double theta = acos(t);
        theta = fmin(fmax(theta, EPS), PI - EPS);
        double numerator = 30.0 * (cos(theta + 0.5) - 0.35);
        double denominator = exp(numerator) + sum_others;
        g_row_loss[row] = numerator - log(denominator);
    }

    // ---- last-block-done final reduction (deterministic fixed-order sum) ----
    __threadfence();
    __shared__ bool is_last;
    if (tid == 0)
        is_last = (atomicAdd(&g_done, 1u) == (unsigned)(gridDim.x - 1));
    __syncthreads();

    if (is_last) {
        double d = 0.0;
        for (int j = tid; j < B; j += NTHR)
            d += g_row_loss[j];

        #pragma unroll
        for (int o = 16; o > 0; o >>= 1)
            d += __shfl_xor_sync(0xffffffffu, d, o);

        __shared__ double dwarp[NWARP];
        if (lid == 0) dwarp[wid] = d;
        __syncthreads();

        if (tid == 0) {
            double tot = 0.0;
            #pragma unroll
            for (int w = 0; w < NWARP; w++) tot += dwarp[w];
            out[0] = (float)(-tot / (double)B);
            g_done = 0;   // reset for next graph replay
        }
    }
}

extern "C" void kernel_launch(void* const* d_in, const int* in_sizes, int n_in,
                              void* d_out, int out_size)
{
    const float* preds  = (const float*)d_in[0];
    const int*   labels = (const int*)d_in[1];

    const int B = in_sizes[1];                 // 2048
    const int V = in_sizes[0] / B;             // 32000

    cosarc_fused_kernel<<<B, NTHR>>>(preds, labels, (float*)d_out, V, B);
}

// round 10
// speedup vs baseline: 1.0086x; 1.0086x over previous
#include <cuda_runtime.h>
#include <cuda_bf16.h>

#define MAX_ROWS 8192
#define NTHR 320
#define NWARP (NTHR / 32)

__device__ double g_row_loss[MAX_ROWS];
__device__ unsigned int g_done = 0;   // self-resets -> graph-replay safe

__device__ __forceinline__ float ex2(float x) {
    float y;
    asm("ex2.approx.f32 %0, %1;" : "=f"(y) : "f"(x));
    return y;
}

// Blackwell 256-bit load: one instruction / one SB slot per 32B per thread
// -> 1KB in flight per warp-load, 2x the depth-1 outstanding bytes of LDG.128.
__device__ __forceinline__ void ldg256(const float* __restrict__ p, float* v) {
    asm volatile("ld.global.nc.v8.f32 {%0,%1,%2,%3,%4,%5,%6,%7}, [%8];"
        : "=f"(v[0]), "=f"(v[1]), "=f"(v[2]), "=f"(v[3]),
          "=f"(v[4]), "=f"(v[5]), "=f"(v[6]), "=f"(v[7])
        : "l"(p));
}

// One 320-thread block per row. R3-R9 post-mortem: delivered BW ~= in-flight
// bytes / loaded latency; all designs sat at ~27KB/SM in flight (depth-1
// 512B chunks) -> 4.9 TB/s. LDG.E.256 doubles in-flight bytes at identical
// warp count and near-identical register cost.
__global__ void __launch_bounds__(NTHR, 6) cosarc_fused_kernel(
    const float* __restrict__ preds,
    const int* __restrict__ labels,     // int32 (JAX x64 disabled)
    float* __restrict__ out,
    int V, int B)
{
    const int tid = threadIdx.x;
    const int wid = tid >> 5;
    const int lid = tid & 31;
    const int row = blockIdx.x;
    const float* rp = preds + (size_t)row * (size_t)V;

    const float C = 30.0f * 1.4426950408889634f;   // exp(30x) = exp2(C*x)
    float s0 = 0.f, s1 = 0.f, s2 = 0.f, s3 = 0.f;

    if (V == 32000) {
        // 4000 float8 per row: 12 full strides of 320, then 160 remainder.
        const float* p = rp + tid * 8;
        float v[8];
        #pragma unroll
        for (int k = 0; k < 12; k++) {
            ldg256(p + k * (NTHR * 8), v);
            s0 += ex2(v[0] * C) + ex2(v[4] * C);
            s1 += ex2(v[1] * C) + ex2(v[5] * C);
            s2 += ex2(v[2] * C) + ex2(v[6] * C);
            s3 += ex2(v[3] * C) + ex2(v[7] * C);
        }
        if (tid < 160) {
            ldg256(rp + (3840 + tid) * 8, v);
            s0 += ex2(v[0] * C) + ex2(v[4] * C);
            s1 += ex2(v[1] * C) + ex2(v[5] * C);
            s2 += ex2(v[2] * C) + ex2(v[6] * C);
            s3 += ex2(v[3] * C) + ex2(v[7] * C);
        }
    } else {
        const float4* p4 = reinterpret_cast<const float4*>(rp);
        const int n4 = V >> 2;
        for (int i = tid; i < n4; i += NTHR) {
            float4 v = __ldg(&p4[i]);
            s0 += ex2(v.x * C);
            s1 += ex2(v.y * C);
            s2 += ex2(v.z * C);
            s3 += ex2(v.w * C);
        }
        for (int j = (n4 << 2) + tid; j < V; j += NTHR)
            s0 += ex2(rp[j] * C);
    }

    float sum = (s0 + s1) + (s2 + s3);

    #pragma unroll
    for (int o = 16; o > 0; o >>= 1)
        sum += __shfl_xor_sync(0xffffffffu, sum, o);

    __shared__ float warpsum[NWARP];
    if (lid == 0) warpsum[wid] = sum;
    __syncthreads();

    if (tid == 0) {
        float tot = 0.f;
        #pragma unroll
        for (int w = 0; w < NWARP; w++) tot += warpsum[w];

        int lab = labels[row];
        if (lab < 0) lab = 0;
        if (lab >= V) lab = V - 1;
        const float target = rp[lab];

        double sum_others = (double)tot - (double)ex2(target * C);

        const double EPS = 1e-12;
        const double PI  = 3.14159265358979323846;
        double t = (double)target;
        t = fmin(fmax(t, -1.0 + EPS), 1.0 - EPS);
        double theta = acos(t);
        theta = fmin(fmax(theta, EPS), PI - EPS);
        double numerator = 30.0 * (cos(theta + 0.5) - 0.35);
        double denominator = exp(numerator) + sum_others;
        g_row_loss[row] = numerator - log(denominator);
    }

    // ---- last-block-done final reduction (deterministic fixed-order sum) ----
    __threadfence();
    __shared__ bool is_last;
    if (tid == 0)
        is_last = (atomicAdd(&g_done, 1u) == (unsigned)(gridDim.x - 1));
    __syncthreads();

    if (is_last) {
        double d = 0.0;
        for (int j = tid; j < B; j += NTHR)
            d += g_row_loss[j];

        #pragma unroll
        for (int o = 16; o > 0; o >>= 1)
            d += __shfl_xor_sync(0xffffffffu, d, o);

        __shared__ double dwarp[NWARP];
        if (lid == 0) dwarp[wid] = d;
        __syncthreads();

        if (tid == 0) {
            double tot = 0.0;
            #pragma unroll
            for (int w = 0; w < NWARP; w++) tot += dwarp[w];
            out[0] = (float)(-tot / (double)B);
            g_done = 0;   // reset for next graph replay
        }
    }
}

extern "C" void kernel_launch(void* const* d_in, const int* in_sizes, int n_in,
                              void* d_out, int out_size)
{
    const float* preds  = (const float*)d_in[0];
    const int*   labels = (const int*)d_in[1];

    const int B = in_sizes[1];                 // 2048
    const int V = in_sizes[0] / B;             // 32000

    cosarc_fused_kernel<<<B, NTHR>>>(preds, labels, (float*)d_out, V, B);
}

// round 11
// speedup vs baseline: 1.0374x; 1.0286x over previous
#include <cuda_runtime.h>
#include <cuda_bf16.h>

#define MAX_ROWS 8192
#define NTHR   288            // 8 consumer warps (256 thr) + 1 producer warp
#define NWARP  9
#define TILE_F 2048           // floats per tile (8 KB)
#define NSLOT  3              // SMEM ring slots (24 KB)

__device__ double g_row_loss[MAX_ROWS];
__device__ unsigned int g_done = 0;   // self-resets -> graph-replay safe

__device__ __forceinline__ float ex2(float x) {
    float y; asm("ex2.approx.f32 %0, %1;" : "=f"(y) : "f"(x)); return y;
}
__device__ __forceinline__ unsigned int smem_u32(const void* p) {
    return (unsigned int)__cvta_generic_to_shared(p);
}
__device__ __forceinline__ void mbar_init(unsigned int bar, unsigned int cnt) {
    asm volatile("mbarrier.init.shared.b64 [%0], %1;" :: "r"(bar), "r"(cnt) : "memory");
}
__device__ __forceinline__ void mbar_arrive(unsigned int bar) {
    asm volatile("mbarrier.arrive.shared.b64 _, [%0];" :: "r"(bar) : "memory");
}
__device__ __forceinline__ void mbar_wait(unsigned int bar, unsigned int parity) {
    asm volatile(
        "{\n\t.reg .pred P1;\n\t"
        "WL_%=:\n\t"
        "mbarrier.try_wait.parity.acquire.cta.shared::cta.b64 P1, [%0], %1, 0x989680;\n\t"
        "@P1 bra.uni WD_%=;\n\t"
        "bra.uni WL_%=;\n\t"
        "WD_%=:\n\t}"
        :: "r"(bar), "r"(parity) : "memory");
}

// Warp-specialized producer/consumer per row. Producer warp ONLY issues
// cp.async tiles (its issue rate is never blocked by the MUFU consume chain
// — the coupling that capped R3-R10 at ~27KB/SM in flight / 4.9 TB/s).
// Consumers ONLY read SMEM + exp. Ring handshake via mbarrier (no
// __syncthreads in the hot loop).
__global__ void __launch_bounds__(NTHR, 6) cosarc_fused_kernel(
    const float* __restrict__ preds,
    const int* __restrict__ labels,     // int32 (JAX x64 disabled)
    float* __restrict__ out,
    int V, int B)
{
    __shared__ __align__(128) float buf[NSLOT][TILE_F];
    __shared__ __align__(8) unsigned long long fullb[NSLOT], emptyb[NSLOT];
    __shared__ float warpsum[8];

    const int tid = threadIdx.x;
    const int wid = tid >> 5;
    const int lid = tid & 31;
    const int row = blockIdx.x;
    const float* rp = preds + (size_t)row * (size_t)V;
    const int NT = (V + TILE_F - 1) / TILE_F;     // 16 for V=32000

    if (tid == 0) {
        #pragma unroll
        for (int s = 0; s < NSLOT; s++) {
            mbar_init(smem_u32(&fullb[s]), 32);   // producer warp arrives
            mbar_init(smem_u32(&emptyb[s]), 8);   // one elect per consumer warp
        }
    }
    __syncthreads();

    const float C = 30.0f * 1.4426950408889634f;  // exp(30x) = exp2(C*x)
    float s0 = 0.f, s1 = 0.f;

    if (wid == 8) {
        // ------------------- producer warp -------------------
        int slot = 0, phase = 1;                   // first empty-waits pass
        for (int t = 0; t < NT; t++) {
            mbar_wait(smem_u32(&emptyb[slot]), phase);

            int nf = V - t * TILE_F; if (nf > TILE_F) nf = TILE_F;
            int bytes = (nf >> 2) << 4;            // whole float4s only
            const char* src = (const char*)(rp + t * TILE_F);
            unsigned int dst = smem_u32(&buf[slot][0]);
            for (int off = lid * 16; off < bytes; off += 512)
                asm volatile("cp.async.cg.shared.global [%0], [%1], 16;"
                             :: "r"(dst + off), "l"(src + off) : "memory");
            asm volatile("cp.async.commit_group;" ::: "memory");

            if (t >= 1) {                          // group t-1 complete -> announce
                asm volatile("cp.async.wait_group 1;" ::: "memory");
                int ps = slot - 1; if (ps < 0) ps = NSLOT - 1;
                mbar_arrive(smem_u32(&fullb[ps]));
            }
            if (++slot == NSLOT) { slot = 0; phase ^= 1; }
        }
        asm volatile("cp.async.wait_group 0;" ::: "memory");
        int ls = (NT - 1) % NSLOT;
        mbar_arrive(smem_u32(&fullb[ls]));
    } else {
        // ------------------- 8 consumer warps -------------------
        int slot = 0, phase = 0;
        for (int t = 0; t < NT; t++) {
            mbar_wait(smem_u32(&fullb[slot]), phase);

            int nf = V - t * TILE_F; if (nf > TILE_F) nf = TILE_F;
            int n4 = nf >> 2;
            const float4* bp = reinterpret_cast<const float4*>(&buf[slot][0]);
            for (int i = tid; i < n4; i += 256) {
                float4 v = bp[i];
                s0 += ex2(v.x * C) + ex2(v.y * C);
                s1 += ex2(v.z * C) + ex2(v.w * C);
            }
            __syncwarp();
            if (lid == 0) mbar_arrive(smem_u32(&emptyb[slot]));
            if (++slot == NSLOT) { slot = 0; phase ^= 1; }
        }
        // Scalar tail (V % 4 != 0) straight from global — not hit for V=32000.
        for (int j = (V & ~3) + tid; j < V; j += 256)
            s0 += ex2(rp[j] * C);
    }

    float sum = s0 + s1;
    #pragma unroll
    for (int o = 16; o > 0; o >>= 1)
        sum += __shfl_xor_sync(0xffffffffu, sum, o);
    if (wid < 8 && lid == 0) warpsum[wid] = sum;
    __syncthreads();

    if (tid == 0) {
        float tot = 0.f;
        #pragma unroll
        for (int w = 0; w < 8; w++) tot += warpsum[w];

        int lab = labels[row];
        if (lab < 0) lab = 0;
        if (lab >= V) lab = V - 1;
        const float target = rp[lab];

        double sum_others = (double)tot - (double)ex2(target * C);

        const double EPS = 1e-12;
        const double PI  = 3.14159265358979323846;
        double t = (double)target;
        t = fmin(fmax(t, -1.0 + EPS), 1.0 - EPS);
        double theta = acos(t);
        theta = fmin(fmax(theta, EPS), PI - EPS);
        double numerator = 30.0 * (cos(theta + 0.5) - 0.35);
        double denominator = exp(numerator) + sum_others;
        g_row_loss[row] = numerator - log(denominator);
    }

    // ---- last-block-done final reduction (deterministic fixed-order sum) ----
    __threadfence();
    __shared__ bool is_last;
    if (tid == 0)
        is_last = (atomicAdd(&g_done, 1u) == (unsigned)(gridDim.x - 1));
    __syncthreads();

    if (is_last) {
        double d = 0.0;
        for (int j = tid; j < B; j += NTHR)
            d += g_row_loss[j];
        #pragma unroll
        for (int o = 16; o > 0; o >>= 1)
            d += __shfl_xor_sync(0xffffffffu, d, o);

        __shared__ double dwarp[NWARP];
        if (lid == 0) dwarp[wid] = d;
        __syncthreads();

        if (tid == 0) {
            double tot = 0.0;
            #pragma unroll
            for (int w = 0; w < NWARP; w++) tot += dwarp[w];
            out[0] = (float)(-tot / (double)B);
            g_done = 0;   // reset for next graph replay
        }
    }
}

extern "C" void kernel_launch(void* const* d_in, const int* in_sizes, int n_in,
                              void* d_out, int out_size)
{
    const float* preds  = (const float*)d_in[0];
    const int*   labels = (const int*)d_in[1];

    const int B = in_sizes[1];                 // 2048
    const int V = in_sizes[0] / B;             // 32000

    cosarc_fused_kernel<<<B, NTHR>>>(preds, labels, (float*)d_out, V, B);
}

// round 12
// speedup vs baseline: 1.0508x; 1.0128x over previous
#include <cuda_runtime.h>
#include <cuda_bf16.h>

#define MAX_ROWS 8192
#define STAGES 4      // cp.async pipeline depth (groups in flight)
#define NSLOTS 6      // SMEM ring slots (> STAGES+1: safe WAR reuse distance)
#define PD     8      // L2-prefetch distance beyond the cp.async window (chunks)

__device__ double g_row_loss[MAX_ROWS];
__device__ unsigned int g_done = 0;   // self-resets each run -> graph-replay safe

__device__ __forceinline__ float ex2(float x) {
    float y;
    asm("ex2.approx.f32 %0, %1;" : "=f"(y) : "f"(x));
    return y;
}
__device__ __forceinline__ void pf_l2(const void* p) {
    asm volatile("prefetch.global.L2 [%0];" :: "l"(p));
}

// R5 champion structure (cp.async per-thread ring, 55.8us) + DEDUPED L2
// prefetch: lanes 0-3 prefetch the four 128B lines of the chunk PD ahead of
// the cp.async window (R9 showed prefetch lifts DRAM to 4.9TB/s but per-lane
// duplication wasted 8% of DRAM traffic and lost the win).
__global__ void __launch_bounds__(256) cosarc_fused_kernel(
    const float* __restrict__ preds,
    const int* __restrict__ labels,     // int32 (JAX x64 disabled)
    float* __restrict__ out,
    int V, int B)
{
    __shared__ float4 buf[NSLOTS][256];

    const int tid = threadIdx.x;
    const int wid = tid >> 5;
    const int lid = tid & 31;
    const int row = blockIdx.x;
    const float* rp = preds + (size_t)row * (size_t)V;
    const float4* p4 = reinterpret_cast<const float4*>(rp);
    const int n4 = V >> 2;

    // Per-warp contiguous range of float4s (8 warps/block): coalesced 512B chunks.
    const int start = (int)(((long long)n4 * wid) >> 3);
    const int end   = (int)(((long long)n4 * (wid + 1)) >> 3);
    const int chunks = (end - start + 31) >> 5;

    const float C = 30.0f * 1.4426950408889634f;   // exp(30x) = exp2(C*x)
    float s0 = 0.f, s1 = 0.f;

    // Prologue: issue chunks 0..STAGES-1 (predicated per-lane), one group each,
    // and prefetch the following PD chunks (one lane per 128B line).
    #pragma unroll
    for (int s = 0; s < STAGES; s++) {
        int g = start + s * 32 + lid;
        if (s < chunks && g < end) {
            unsigned int dst = (unsigned int)__cvta_generic_to_shared(&buf[s % NSLOTS][tid]);
            asm volatile("cp.async.cg.shared.global [%0], [%1], 16;"
                         :: "r"(dst), "l"(p4 + g) : "memory");
        }
        asm volatile("cp.async.commit_group;" ::: "memory");
    }
    if (lid < 4) {
        #pragma unroll
        for (int s = STAGES; s < STAGES + PD; s++) {
            if (s < chunks)
                pf_l2((const char*)(p4 + start + s * 32) + lid * 128);
        }
    }

    for (int c = 0; c < chunks; c++) {
        // Wait until <= STAGES-1 groups pending -> chunk c's group is done.
        asm volatile("cp.async.wait_group %0;" :: "n"(STAGES - 1) : "memory");

        int g = start + c * 32 + lid;
        if (g < end) {
            float4 v = buf[c % NSLOTS][tid];
            s0 += ex2(v.x * C) + ex2(v.y * C);
            s1 += ex2(v.z * C) + ex2(v.w * C);
        }

        // Issue chunk c+STAGES (L2-hot by now thanks to the prefetch stream).
        int nc = c + STAGES;
        int gn = start + nc * 32 + lid;
        if (nc < chunks && gn < end) {
            unsigned int dst = (unsigned int)__cvta_generic_to_shared(&buf[nc % NSLOTS][tid]);
            asm volatile("cp.async.cg.shared.global [%0], [%1], 16;"
                         :: "r"(dst), "l"(p4 + gn) : "memory");
        }
        asm volatile("cp.async.commit_group;" ::: "memory");

        // Prefetch chunk c+STAGES+PD: exactly one prefetch per 128B line.
        int pc = c + STAGES + PD;
        if (lid < 4 && pc < chunks)
            pf_l2((const char*)(p4 + start + pc * 32) + lid * 128);
    }
    // Scalar tail (V % 4 != 0) — not hit for V=32000.
    for (int j = (n4 << 2) + tid; j < V; j += 256)
        s0 += ex2(rp[j] * C);

    float sum = s0 + s1;

    #pragma unroll
    for (int o = 16; o > 0; o >>= 1)
        sum += __shfl_xor_sync(0xffffffffu, sum, o);

    __shared__ float warpsum[8];
    if (lid == 0) warpsum[wid] = sum;
    __syncthreads();

    if (tid == 0) {
        float tot = 0.f;
        #pragma unroll
        for (int w = 0; w < 8; w++) tot += warpsum[w];

        int lab = labels[row];
        if (lab < 0) lab = 0;
        if (lab >= V) lab = V - 1;
        const float target = rp[lab];

        double sum_others = (double)tot - (double)ex2(target * C);

        const double EPS = 1e-12;
        const double PI  = 3.14159265358979323846;
        double t = (double)target;
        t = fmin(fmax(t, -1.0 + EPS), 1.0 - EPS);
        double theta = acos(t);
        theta = fmin(fmax(theta, EPS), PI - EPS);
        double numerator = 30.0 * (cos(theta + 0.5) - 0.35);
        double denominator = exp(numerator) + sum_others;
        g_row_loss[row] = numerator - log(denominator);
    }

    // ---- last-block-done final reduction (deterministic fixed-order sum) ----
    __threadfence();
    __shared__ bool is_last;
    if (tid == 0)
        is_last = (atomicAdd(&g_done, 1u) == (unsigned)(gridDim.x - 1));
    __syncthreads();

    if (is_last) {
        double d = 0.0;
        for (int j = tid; j < B; j += 256)
            d += g_row_loss[j];

        #pragma unroll
        for (int o = 16; o > 0; o >>= 1)
            d += __shfl_xor_sync(0xffffffffu, d, o);

        __shared__ double dwarp[8];
        if (lid == 0) dwarp[wid] = d;
        __syncthreads();

        if (tid == 0) {
            double tot = 0.0;
            #pragma unroll
            for (int w = 0; w < 8; w++) tot += dwarp[w];
            out[0] = (float)(-tot / (double)B);
            g_done = 0;   // reset for next graph replay
        }
    }
}

extern "C" void kernel_launch(void* const* d_in, const int* in_sizes, int n_in,
                              void* d_out, int out_size)
{
    const float* preds  = (const float*)d_in[0];
    const int*   labels = (const int*)d_in[1];

    const int B = in_sizes[1];                 // 2048
    const int V = in_sizes[0] / B;             // 32000

    cosarc_fused_kernel<<<B, 256>>>(preds, labels, (float*)d_out, V, B);
}